// round 1
// baseline (speedup 1.0000x reference)
#include <cuda_runtime.h>
#include <cstdint>

// Problem constants
#define BB 8
#define NN 8192
#define NG 512
#define GS 32

// Scratch: transformed points (float4 for vectorized loads). 1 MB.
__device__ float4 g_x[BB * NN];

// ---------------------------------------------------------------------------
// Kernel 1: SE3 transform.  x = R @ p + t  (FMA chain, matching gemm lowering)
// ---------------------------------------------------------------------------
__global__ void xform_k(const float* __restrict__ xyz,
                        const float* __restrict__ pose) {
    int i = blockIdx.x * blockDim.x + threadIdx.x;
    if (i >= BB * NN) return;
    int b = i >> 13;  // /NN
    const float* P = pose + b * 12;
    float x = xyz[3 * i + 0];
    float y = xyz[3 * i + 1];
    float z = xyz[3 * i + 2];
    float r0 = __fadd_rn(__fmaf_rn(__ldg(P + 2), z,
               __fmaf_rn(__ldg(P + 1), y, __fmul_rn(__ldg(P + 0), x))), __ldg(P + 3));
    float r1 = __fadd_rn(__fmaf_rn(__ldg(P + 6), z,
               __fmaf_rn(__ldg(P + 5), y, __fmul_rn(__ldg(P + 4), x))), __ldg(P + 7));
    float r2 = __fadd_rn(__fmaf_rn(__ldg(P + 10), z,
               __fmaf_rn(__ldg(P + 9), y, __fmul_rn(__ldg(P + 8), x))), __ldg(P + 11));
    g_x[i] = make_float4(r0, r1, r2, 0.0f);
}

// ---------------------------------------------------------------------------
// Kernel 2: farthest point sampling. One CTA (1024 thr) per batch.
// Points + running min-dist live in registers (8 per thread).
// Argmax key: (dist_bits << 32) | (8191 - idx)  -> max == (max dist, min idx)
// Writes the 512 center coordinates directly into d_out's center region.
// ---------------------------------------------------------------------------
__global__ __launch_bounds__(1024, 1) void fps_k(float* __restrict__ center_out) {
    const int b = blockIdx.x;
    const int tid = threadIdx.x;

    __shared__ unsigned long long s_red[32];
    __shared__ unsigned long long s_best;
    __shared__ float s_cx, s_cy, s_cz;

    float px[8], py[8], pz[8], dst[8];
#pragma unroll
    for (int s = 0; s < 8; s++) {
        float4 p = g_x[b * NN + s * 1024 + tid];
        px[s] = p.x; py[s] = p.y; pz[s] = p.z;
        dst[s] = 1e10f;
    }

    if (tid == 0) {
        // first center is index 0 (held by thread 0, slot 0)
        s_cx = px[0]; s_cy = py[0]; s_cz = pz[0];
        float* c = center_out + (b * NG + 0) * 3;
        c[0] = px[0]; c[1] = py[0]; c[2] = pz[0];
    }
    __syncthreads();

    for (int g = 0; g < NG; g++) {
        const float lx = s_cx, ly = s_cy, lz = s_cz;
        unsigned long long best = 0ull;
#pragma unroll
        for (int s = 0; s < 8; s++) {
            float dx = __fsub_rn(px[s], lx);
            float dy = __fsub_rn(py[s], ly);
            float dz = __fsub_rn(pz[s], lz);
            // no-FMA sum of squares: (dx*dx + dy*dy) + dz*dz
            float d = __fadd_rn(__fadd_rn(__fmul_rn(dx, dx), __fmul_rn(dy, dy)),
                                __fmul_rn(dz, dz));
            dst[s] = fminf(dst[s], d);
            unsigned idx = (unsigned)(s * 1024 + tid);
            unsigned long long k =
                ((unsigned long long)__float_as_uint(dst[s]) << 32) | (8191u - idx);
            best = best > k ? best : k;
        }
        // two-level block argmax
#pragma unroll
        for (int o = 16; o > 0; o >>= 1) {
            unsigned long long v = __shfl_xor_sync(0xffffffffu, best, o);
            best = best > v ? best : v;
        }
        if ((tid & 31) == 0) s_red[tid >> 5] = best;
        __syncthreads();
        if (tid < 32) {
            unsigned long long v = s_red[tid];
#pragma unroll
            for (int o = 16; o > 0; o >>= 1) {
                unsigned long long w = __shfl_xor_sync(0xffffffffu, v, o);
                v = v > w ? v : w;
            }
            if (tid == 0) s_best = v;
        }
        __syncthreads();

        if (g < NG - 1) {
            unsigned bidx = 8191u - (unsigned)(s_best & 0xffffffffu);
            if (tid == (int)(bidx & 1023u)) {
                int slot = (int)(bidx >> 10);
#pragma unroll
                for (int s = 0; s < 8; s++) {
                    if (s == slot) {
                        s_cx = px[s]; s_cy = py[s]; s_cz = pz[s];
                        float* c = center_out + (b * NG + g + 1) * 3;
                        c[0] = px[s]; c[1] = py[s]; c[2] = pz[s];
                    }
                }
            }
            __syncthreads();
        }
    }
}

// ---------------------------------------------------------------------------
// Kernel 3: exact 32-NN per center. One warp per center (8 warps / 256-thr CTA).
// Each lane owns 256 interleaved points, keeps a sorted top-4 (registers),
// 32 extraction rounds of warp-min over (dist,idx) keys; rare per-lane rescan
// (mask-tracked) when a lane contributes >4 of the 32 winners.
// Key: (dist_bits << 32) | idx  -> min == (min dist, min idx)  [top_k stable]
// ---------------------------------------------------------------------------
__device__ __forceinline__ void ins4(unsigned long long k,
                                     unsigned long long& k0, unsigned long long& k1,
                                     unsigned long long& k2, unsigned long long& k3) {
    if (k < k3) {
        if (k < k2) {
            k3 = k2;
            if (k < k1) {
                k2 = k1;
                if (k < k0) { k1 = k0; k0 = k; } else { k1 = k; }
            } else { k2 = k; }
        } else { k3 = k; }
    }
}

__global__ __launch_bounds__(256) void knn_k(const float* __restrict__ center,
                                             float* __restrict__ neigh) {
    const int warp = threadIdx.x >> 5;
    const int lane = threadIdx.x & 31;
    const int c = blockIdx.x * 8 + warp;   // 0..4095
    const int b = c >> 9;                  // /NG

    const float cx = __ldg(center + c * 3 + 0);
    const float cy = __ldg(center + c * 3 + 1);
    const float cz = __ldg(center + c * 3 + 2);
    const float4* xp = g_x + b * NN;

    const unsigned long long SENT = ~0ull;
    unsigned long long k0 = SENT, k1 = SENT, k2 = SENT, k3 = SENT;
    unsigned mask[8] = {0, 0, 0, 0, 0, 0, 0, 0};

    // initial scan: each lane over its 256 interleaved points
    for (int i = 0; i < 256; i++) {
        int idx = i * 32 + lane;
        float4 p = __ldg(&xp[idx]);
        float dx = __fsub_rn(cx, p.x);
        float dy = __fsub_rn(cy, p.y);
        float dz = __fsub_rn(cz, p.z);
        float d = __fadd_rn(__fadd_rn(__fmul_rn(dx, dx), __fmul_rn(dy, dy)),
                            __fmul_rn(dz, dz));
        unsigned long long k =
            ((unsigned long long)__float_as_uint(d) << 32) | (unsigned)idx;
        ins4(k, k0, k1, k2, k3);
    }

    unsigned my_out_idx = 0;
    for (int r = 0; r < 32; r++) {
        unsigned long long h = k0;
        unsigned long long best = h;
#pragma unroll
        for (int o = 16; o > 0; o >>= 1) {
            unsigned long long v = __shfl_xor_sync(0xffffffffu, best, o);
            best = best < v ? best : v;
        }
        if (lane == r) my_out_idx = (unsigned)(best & 0xffffffffu);

        if (h == best) {  // unique winner (keys carry unique idx)
            k0 = k1; k1 = k2; k2 = k3; k3 = SENT;
            unsigned idx = (unsigned)(best & 0xffffffffu);
            int slot = (int)(idx >> 5);        // which of my 256 points
#pragma unroll
            for (int w = 0; w < 8; w++)
                if (w == (slot >> 5)) mask[w] |= (1u << (slot & 31));

            if (k0 == SENT) {  // rare: rebuild top-4 of non-extracted points
#pragma unroll
                for (int w = 0; w < 8; w++) {
                    unsigned m = mask[w];
                    for (int j = 0; j < 32; j++) {
                        if ((m >> j) & 1u) continue;
                        int pi = ((w << 5) + j) * 32 + lane;
                        float4 p = __ldg(&xp[pi]);
                        float dx = __fsub_rn(cx, p.x);
                        float dy = __fsub_rn(cy, p.y);
                        float dz = __fsub_rn(cz, p.z);
                        float d = __fadd_rn(
                            __fadd_rn(__fmul_rn(dx, dx), __fmul_rn(dy, dy)),
                            __fmul_rn(dz, dz));
                        unsigned long long k =
                            ((unsigned long long)__float_as_uint(d) << 32) |
                            (unsigned)pi;
                        ins4(k, k0, k1, k2, k3);
                    }
                }
            }
        }
        __syncwarp(0xffffffffu);
    }

    // gather: lane r writes neighbor r of this center
    float4 p = __ldg(&xp[my_out_idx]);
    float* o = neigh + ((size_t)c * 32 + lane) * 3;
    o[0] = p.x; o[1] = p.y; o[2] = p.z;
}

// ---------------------------------------------------------------------------
// Launch
// ---------------------------------------------------------------------------
extern "C" void kernel_launch(void* const* d_in, const int* in_sizes, int n_in,
                              void* d_out, int out_size) {
    const float* xyz  = (const float*)d_in[0];
    const float* pose = (const float*)d_in[1];
    if (n_in >= 2 && in_sizes[0] == BB * 12) {  // defensive: swap if order reversed
        xyz  = (const float*)d_in[1];
        pose = (const float*)d_in[0];
    }
    float* out = (float*)d_out;
    float* neigh  = out;                        // [B, NG, GS, 3] = 393216 floats
    float* center = out + (size_t)BB * NG * GS * 3;  // [B, NG, 3] = 12288 floats

    xform_k<<<(BB * NN + 255) / 256, 256>>>(xyz, pose);
    fps_k<<<BB, 1024>>>(center);
    knn_k<<<(BB * NG) / 8, 256>>>(center, neigh);
}

// round 2
// speedup vs baseline: 1.0685x; 1.0685x over previous
#include <cuda_runtime.h>
#include <cstdint>

#define BB 8
#define NN 8192
#define NG 512
#define GS 32

// Scratch: transformed points (float4 for vectorized loads). 1 MB.
__device__ float4 g_x[BB * NN];

// packed f32x2 helpers (per-lane IEEE rn — bit-identical to scalar __fadd_rn/__fmul_rn)
#define MUL2(out, a, b) asm("mul.rn.f32x2 %0, %1, %2;" : "=l"(out) : "l"(a), "l"(b))
#define ADD2(out, a, b) asm("add.rn.f32x2 %0, %1, %2;" : "=l"(out) : "l"(a), "l"(b))
#define PACK2(out, lo, hi) asm("mov.b64 %0, {%1, %2};" : "=l"(out) : "r"(lo), "r"(hi))
#define UNPACK2(lo, hi, in) asm("mov.b64 {%0, %1}, %2;" : "=r"(lo), "=r"(hi) : "l"(in))

// ---------------------------------------------------------------------------
// Kernel 1: SE3 transform.  x = R @ p + t
// ---------------------------------------------------------------------------
__global__ void xform_k(const float* __restrict__ xyz,
                        const float* __restrict__ pose) {
    int i = blockIdx.x * blockDim.x + threadIdx.x;
    if (i >= BB * NN) return;
    int b = i >> 13;
    const float* P = pose + b * 12;
    float x = xyz[3 * i + 0];
    float y = xyz[3 * i + 1];
    float z = xyz[3 * i + 2];
    float r0 = __fadd_rn(__fmaf_rn(__ldg(P + 2), z,
               __fmaf_rn(__ldg(P + 1), y, __fmul_rn(__ldg(P + 0), x))), __ldg(P + 3));
    float r1 = __fadd_rn(__fmaf_rn(__ldg(P + 6), z,
               __fmaf_rn(__ldg(P + 5), y, __fmul_rn(__ldg(P + 4), x))), __ldg(P + 7));
    float r2 = __fadd_rn(__fmaf_rn(__ldg(P + 10), z,
               __fmaf_rn(__ldg(P + 9), y, __fmul_rn(__ldg(P + 8), x))), __ldg(P + 11));
    g_x[i] = make_float4(r0, r1, r2, 0.0f);
}

// ---------------------------------------------------------------------------
// Kernel 2: FPS. One CTA (1024 thr) per batch; 8 points/thread in registers
// (packed as f32x2 pairs). One __syncthreads per iteration:
//   - center broadcast via uniform __ldg of g_x[winner_idx] (L1-resident)
//   - block argmax via warp butterfly + 32 leader atomicMax(ull) into a
//     double-buffered, iteration-tagged key (no reset, no second barrier).
// Key: (g+1)<<45 | dist_bits<<13 | (8191-idx)  -> max == (max dist, min idx)
// ---------------------------------------------------------------------------
__global__ __launch_bounds__(1024, 1) void fps_k(float* __restrict__ center_out) {
    const int b = blockIdx.x;
    const int tid = threadIdx.x;
    __shared__ unsigned long long s_key[2];

    const float4* __restrict__ xp = g_x + b * NN;

    // load 8 points/thread, pack into f32x2 pairs (slots 2j, 2j+1)
    unsigned long long px2[4], py2[4], pz2[4];
    float dst[8];
    {
        float px[8], py[8], pz[8];
#pragma unroll
        for (int s = 0; s < 8; s++) {
            float4 p = xp[s * 1024 + tid];
            px[s] = p.x; py[s] = p.y; pz[s] = p.z;
            dst[s] = 1e10f;
        }
#pragma unroll
        for (int j = 0; j < 4; j++) {
            PACK2(px2[j], __float_as_uint(px[2 * j]), __float_as_uint(px[2 * j + 1]));
            PACK2(py2[j], __float_as_uint(py[2 * j]), __float_as_uint(py[2 * j + 1]));
            PACK2(pz2[j], __float_as_uint(pz[2 * j]), __float_as_uint(pz[2 * j + 1]));
        }
    }

    if (tid == 0) {
        s_key[0] = 0ull;
        s_key[1] = 0ull;
        float4 c0 = __ldg(&xp[0]);
        center_out[(b * NG) * 3 + 0] = c0.x;
        center_out[(b * NG) * 3 + 1] = c0.y;
        center_out[(b * NG) * 3 + 2] = c0.z;
    }
    __syncthreads();

    unsigned widx = 0;  // current center index (uniform)

    for (int g = 0; g < NG - 1; g++) {
        // uniform broadcast load of current center (L1 hit)
        float4 c = __ldg(&xp[widx]);
        unsigned long long ncx, ncy, ncz;
        {
            unsigned nx = __float_as_uint(-c.x);
            unsigned ny = __float_as_uint(-c.y);
            unsigned nz = __float_as_uint(-c.z);
            PACK2(ncx, nx, nx);
            PACK2(ncy, ny, ny);
            PACK2(ncz, nz, nz);
        }

        float lmax = -1.0f;
        int lslot = 0;
#pragma unroll
        for (int j = 0; j < 4; j++) {
            unsigned long long dx, dy, dz, xx, yy, zz, ss, dd;
            ADD2(dx, px2[j], ncx);           // p - c  (exact: add of negation)
            ADD2(dy, py2[j], ncy);
            ADD2(dz, pz2[j], ncz);
            MUL2(xx, dx, dx);
            MUL2(yy, dy, dy);
            ADD2(ss, xx, yy);                // dx*dx + dy*dy
            MUL2(zz, dz, dz);
            ADD2(dd, ss, zz);                // (dx*dx+dy*dy) + dz*dz
            unsigned d0u, d1u;
            UNPACK2(d0u, d1u, dd);
            float d0 = __uint_as_float(d0u);
            float d1 = __uint_as_float(d1u);
            dst[2 * j]     = fminf(dst[2 * j], d0);
            dst[2 * j + 1] = fminf(dst[2 * j + 1], d1);
            if (dst[2 * j] > lmax)     { lmax = dst[2 * j];     lslot = 2 * j; }
            if (dst[2 * j + 1] > lmax) { lmax = dst[2 * j + 1]; lslot = 2 * j + 1; }
        }

        // build 64-bit key: dist_bits<<13 | (8191 - idx)
        unsigned idx = (unsigned)(lslot * 1024 + tid);
        unsigned long long key =
            ((unsigned long long)__float_as_uint(lmax) << 13) | (8191u - idx);

        // warp butterfly max
#pragma unroll
        for (int o = 16; o > 0; o >>= 1) {
            unsigned long long v = __shfl_xor_sync(0xffffffffu, key, o);
            key = key > v ? key : v;
        }
        if ((tid & 31) == 0) {
            unsigned long long tagged = key | ((unsigned long long)(g + 1) << 45);
            atomicMax(&s_key[g & 1], tagged);
        }
        __syncthreads();

        unsigned long long win = s_key[g & 1];
        widx = 8191u - (unsigned)(win & 0x1FFFu);

        if (tid == 0) {
            float4 cw = __ldg(&xp[widx]);
            float* o = center_out + (b * NG + g + 1) * 3;
            o[0] = cw.x; o[1] = cw.y; o[2] = cw.z;
        }
    }
}

// ---------------------------------------------------------------------------
// Kernel 3: exact 32-NN per center. One warp per center; lane-local sorted
// top-4 in registers; 32 warp-min extraction rounds; rare exact rescan.
// Key: (dist_bits << 32) | idx -> min == (min dist, min idx) [stable top_k]
// ---------------------------------------------------------------------------
__device__ __forceinline__ void ins4(unsigned long long k,
                                     unsigned long long& k0, unsigned long long& k1,
                                     unsigned long long& k2, unsigned long long& k3) {
    if (k < k3) {
        if (k < k2) {
            k3 = k2;
            if (k < k1) {
                k2 = k1;
                if (k < k0) { k1 = k0; k0 = k; } else { k1 = k; }
            } else { k2 = k; }
        } else { k3 = k; }
    }
}

__global__ __launch_bounds__(256) void knn_k(const float* __restrict__ center,
                                             float* __restrict__ neigh) {
    const int warp = threadIdx.x >> 5;
    const int lane = threadIdx.x & 31;
    const int c = blockIdx.x * 8 + warp;
    const int b = c >> 9;

    const float cx = __ldg(center + c * 3 + 0);
    const float cy = __ldg(center + c * 3 + 1);
    const float cz = __ldg(center + c * 3 + 2);
    const float4* xp = g_x + b * NN;

    const unsigned long long SENT = ~0ull;
    unsigned long long k0 = SENT, k1 = SENT, k2 = SENT, k3 = SENT;
    unsigned mask[8] = {0, 0, 0, 0, 0, 0, 0, 0};

    for (int i = 0; i < 256; i++) {
        int idx = i * 32 + lane;
        float4 p = __ldg(&xp[idx]);
        float dx = __fsub_rn(cx, p.x);
        float dy = __fsub_rn(cy, p.y);
        float dz = __fsub_rn(cz, p.z);
        float d = __fadd_rn(__fadd_rn(__fmul_rn(dx, dx), __fmul_rn(dy, dy)),
                            __fmul_rn(dz, dz));
        unsigned long long k =
            ((unsigned long long)__float_as_uint(d) << 32) | (unsigned)idx;
        ins4(k, k0, k1, k2, k3);
    }

    unsigned my_out_idx = 0;
    for (int r = 0; r < 32; r++) {
        unsigned long long h = k0;
        unsigned long long best = h;
#pragma unroll
        for (int o = 16; o > 0; o >>= 1) {
            unsigned long long v = __shfl_xor_sync(0xffffffffu, best, o);
            best = best < v ? best : v;
        }
        if (lane == r) my_out_idx = (unsigned)(best & 0xffffffffu);

        if (h == best) {
            k0 = k1; k1 = k2; k2 = k3; k3 = SENT;
            unsigned idx = (unsigned)(best & 0xffffffffu);
            int slot = (int)(idx >> 5);
#pragma unroll
            for (int w = 0; w < 8; w++)
                if (w == (slot >> 5)) mask[w] |= (1u << (slot & 31));

            if (k0 == SENT) {  // rare exact rebuild of remaining top-4
#pragma unroll
                for (int w = 0; w < 8; w++) {
                    unsigned m = mask[w];
                    for (int j = 0; j < 32; j++) {
                        if ((m >> j) & 1u) continue;
                        int pi = ((w << 5) + j) * 32 + lane;
                        float4 p = __ldg(&xp[pi]);
                        float dx = __fsub_rn(cx, p.x);
                        float dy = __fsub_rn(cy, p.y);
                        float dz = __fsub_rn(cz, p.z);
                        float d = __fadd_rn(
                            __fadd_rn(__fmul_rn(dx, dx), __fmul_rn(dy, dy)),
                            __fmul_rn(dz, dz));
                        unsigned long long k =
                            ((unsigned long long)__float_as_uint(d) << 32) |
                            (unsigned)pi;
                        ins4(k, k0, k1, k2, k3);
                    }
                }
            }
        }
        __syncwarp(0xffffffffu);
    }

    float4 p = __ldg(&xp[my_out_idx]);
    float* o = neigh + ((size_t)c * 32 + lane) * 3;
    o[0] = p.x; o[1] = p.y; o[2] = p.z;
}

// ---------------------------------------------------------------------------
// Launch
// ---------------------------------------------------------------------------
extern "C" void kernel_launch(void* const* d_in, const int* in_sizes, int n_in,
                              void* d_out, int out_size) {
    const float* xyz  = (const float*)d_in[0];
    const float* pose = (const float*)d_in[1];
    if (n_in >= 2 && in_sizes[0] == BB * 12) {
        xyz  = (const float*)d_in[1];
        pose = (const float*)d_in[0];
    }
    float* out = (float*)d_out;
    float* neigh  = out;
    float* center = out + (size_t)BB * NG * GS * 3;

    xform_k<<<(BB * NN + 255) / 256, 256>>>(xyz, pose);
    fps_k<<<BB, 1024>>>(center);
    knn_k<<<(BB * NG) / 8, 256>>>(center, neigh);
}